// round 15
// baseline (speedup 1.0000x reference)
#include <cuda_runtime.h>
#include <cuda_bf16.h>

#define NUM_CLASSES 4
#define DIMS 256            // floats per row
#define ACC_GRID 592        // 148 SMs * 4 CTAs
#define ACC_THREADS 256     // 8 warps; one warp covers one full row

// Scratch. Zero-initialized at module load; finalize_kernel re-zeroes after
// consuming, so the "zeroed at accum entry" invariant holds for every replay.
__device__ float g_sums[NUM_CLASSES * DIMS];
__device__ float g_counts[NUM_CLASSES];

// 256-bit load (Blackwell LDG.E.256). 32B-aligned: rows are 1KB-aligned,
// lane offset = lane*32B.
__device__ __forceinline__ void ldg256(const float* p, float* v) {
    asm volatile("ld.global.nc.v8.f32 {%0,%1,%2,%3,%4,%5,%6,%7}, [%8];"
                 : "=f"(v[0]), "=f"(v[1]), "=f"(v[2]), "=f"(v[3]),
                   "=f"(v[4]), "=f"(v[5]), "=f"(v[6]), "=f"(v[7])
                 : "l"(p));
}

#define ACC8(a, v) { _Pragma("unroll") for (int j = 0; j < 8; j++) (a)[j] += (v)[j]; }

__global__ __launch_bounds__(ACC_THREADS, 4)
void accum_kernel(const float* __restrict__ feats,
                  const int* __restrict__ labels,
                  int n_rows) {
    const int lane = threadIdx.x & 31;   // 8-float column group 0..31
    const int wid  = threadIdx.x >> 5;   // warp = row sub-slot 0..7
    const int stride = ACC_GRID * 8;
    int row = blockIdx.x * 8 + wid;

    float a0[8] = {0,0,0,0,0,0,0,0}, a1[8] = {0,0,0,0,0,0,0,0};
    float a2[8] = {0,0,0,0,0,0,0,0}, a3[8] = {0,0,0,0,0,0,0,0};
    int cnt0 = 0, cnt1 = 0, cnt2 = 0, cnt3 = 0;

    // ---- chunked main loop: pre-gather 32 labels per warp, then 32 rows ----
    // Lane j holds the label for iteration j of this chunk; shfl broadcasts it.
    // Removes the per-iteration label-load dependency entirely.
    for (; row + 31 * stride < n_rows; row += 32 * stride) {
        const int lab32 = __ldcs(&labels[row + lane * stride]);  // strided gather

        #pragma unroll 8
        for (int j = 0; j < 32; j += 2) {
            const int r0 = row + j * stride, r1 = r0 + stride;
            float v0[8], v1[8];
            ldg256(feats + (size_t)r0 * DIMS + lane * 8, v0);
            ldg256(feats + (size_t)r1 * DIMS + lane * 8, v1);
            const int l0 = __shfl_sync(0xFFFFFFFFu, lab32, j);
            const int l1 = __shfl_sync(0xFFFFFFFFu, lab32, j + 1);

            // Warp-uniform branches (all lanes share the row -> same label).
            if (l0 == 0)      { ACC8(a0, v0); cnt0++; }
            else if (l0 == 1) { ACC8(a1, v0); cnt1++; }
            else if (l0 == 2) { ACC8(a2, v0); cnt2++; }
            else              { ACC8(a3, v0); cnt3++; }

            if (l1 == 0)      { ACC8(a0, v1); cnt0++; }
            else if (l1 == 1) { ACC8(a1, v1); cnt1++; }
            else if (l1 == 2) { ACC8(a2, v1); cnt2++; }
            else              { ACC8(a3, v1); cnt3++; }
        }
    }
    // ---- tail: per-iteration label loads ----
    for (; row < n_rows; row += stride) {
        float v[8];
        ldg256(feats + (size_t)row * DIMS + lane * 8, v);
        const int lab = __ldcs(&labels[row]);
        if (lab == 0)      { ACC8(a0, v); cnt0++; }
        else if (lab == 1) { ACC8(a1, v); cnt1++; }
        else if (lab == 2) { ACC8(a2, v); cnt2++; }
        else               { ACC8(a3, v); cnt3++; }
    }

    // ---- block reduction across the 8 warps, per class, then atomics ----
    __shared__ float sred[8 * DIMS];     // 8 KB

    float* accs[4] = {a0, a1, a2, a3};
    #pragma unroll
    for (int k = 0; k < NUM_CLASSES; k++) {
        float* acc = accs[k];
        #pragma unroll
        for (int j = 0; j < 8; j++)
            sred[wid * DIMS + lane * 8 + j] = acc[j];
        __syncthreads();
        {
            const int col = threadIdx.x;         // 0..255
            float s = 0.f;
            #pragma unroll
            for (int w = 0; w < 8; w++)
                s += sred[w * DIMS + col];
            atomicAdd(&g_sums[k * DIMS + col], s);
        }
        __syncthreads();
    }

    // Counts: lane 0 of each warp holds them; reduce via shared.
    __shared__ int scnt[8][NUM_CLASSES];
    if (lane == 0) {
        scnt[wid][0] = cnt0; scnt[wid][1] = cnt1;
        scnt[wid][2] = cnt2; scnt[wid][3] = cnt3;
    }
    __syncthreads();
    if (threadIdx.x < NUM_CLASSES) {
        int s = 0;
        #pragma unroll
        for (int w = 0; w < 8; w++) s += scnt[w][threadIdx.x];
        atomicAdd(&g_counts[threadIdx.x], (float)s);
    }
}

// One block per class: mean, L2 norm (block reduce), normalize, write out.
// Tail: re-zero the scratch so the next graph replay sees zeroed accumulators.
__global__ __launch_bounds__(DIMS)
void finalize_kernel(float* __restrict__ out, int out_size) {
    const int k = blockIdx.x;       // class
    const int t = threadIdx.x;      // dim 0..255
    const int lane = t & 31, wid = t >> 5;

    const float cnt = g_counts[k];
    const float mean = g_sums[k * DIMS + t] / cnt;

    // Block reduction of mean*mean
    float v = mean * mean;
    #pragma unroll
    for (int off = 16; off > 0; off >>= 1)
        v += __shfl_down_sync(0xFFFFFFFFu, v, off);

    __shared__ float warpsum[8];
    if (lane == 0) warpsum[wid] = v;
    __syncthreads();
    __shared__ float s_norm;
    if (t == 0) {
        float s = 0.f;
        #pragma unroll
        for (int i = 0; i < 8; i++) s += warpsum[i];
        s_norm = fmaxf(sqrtf(s), 1e-12f);
    }
    __syncthreads();

    out[k * DIMS + t] = mean / s_norm;

    // target = arange(4); write as float values if the out buffer includes it.
    if (t == 0 && out_size >= NUM_CLASSES * DIMS + NUM_CLASSES) {
        out[NUM_CLASSES * DIMS + k] = (float)k;
    }

    // Re-zero scratch for the next replay (all reads above are done).
    g_sums[k * DIMS + t] = 0.0f;
    if (t == 0) g_counts[k] = 0.0f;
}

extern "C" void kernel_launch(void* const* d_in, const int* in_sizes, int n_in,
                              void* d_out, int out_size) {
    const float* feats = (const float*)d_in[0];
    const int* labels = (const int*)d_in[1];
    const int n_rows = in_sizes[1];          // labels element count = row count
    float* out = (float*)d_out;

    accum_kernel<<<ACC_GRID, ACC_THREADS>>>(feats, labels, n_rows);
    finalize_kernel<<<NUM_CLASSES, DIMS>>>(out, out_size);
}

// round 16
// speedup vs baseline: 1.0671x; 1.0671x over previous
#include <cuda_runtime.h>
#include <cuda_bf16.h>

#define NUM_CLASSES 4
#define DIMS 256            // floats per row
#define ACC_GRID 592        // 148 SMs * 4 CTAs
#define ACC_THREADS 256     // 8 warps; one warp covers one full row
#define MAX_CHUNK 1792      // label staging chunk (rows); 7 KB smem

// Scratch. Zero-initialized at module load; finalize_kernel re-zeroes after
// consuming, so the "zeroed at accum entry" invariant holds for every replay.
__device__ float g_sums[NUM_CLASSES * DIMS];
__device__ float g_counts[NUM_CLASSES];

// 256-bit load (Blackwell LDG.E.256). 32B-aligned: rows are 1KB-aligned,
// lane offset = lane*32B.
__device__ __forceinline__ void ldg256(const float* p, float* v) {
    asm volatile("ld.global.nc.v8.f32 {%0,%1,%2,%3,%4,%5,%6,%7}, [%8];"
                 : "=f"(v[0]), "=f"(v[1]), "=f"(v[2]), "=f"(v[3]),
                   "=f"(v[4]), "=f"(v[5]), "=f"(v[6]), "=f"(v[7])
                 : "l"(p));
}

#define ACC8(a, v) { _Pragma("unroll") for (int j = 0; j < 8; j++) (a)[j] += (v)[j]; }

__global__ __launch_bounds__(ACC_THREADS, 4)
void accum_kernel(const float* __restrict__ feats,
                  const int* __restrict__ labels,
                  int n_rows) {
    const int lane = threadIdx.x & 31;   // 8-float column group 0..31
    const int wid  = threadIdx.x >> 5;   // warp = row sub-slot 0..7

    // Contiguous slab per block.
    const int slab = (n_rows + ACC_GRID - 1) / ACC_GRID;
    const int slab_begin = blockIdx.x * slab;
    const int slab_end   = min(slab_begin + slab, n_rows);

    __shared__ int s_lab[MAX_CHUNK];

    float a0[8] = {0,0,0,0,0,0,0,0}, a1[8] = {0,0,0,0,0,0,0,0};
    float a2[8] = {0,0,0,0,0,0,0,0}, a3[8] = {0,0,0,0,0,0,0,0};
    int cnt0 = 0, cnt1 = 0, cnt2 = 0, cnt3 = 0;

    for (int cstart = slab_begin; cstart < slab_end; cstart += MAX_CHUNK) {
        const int clen = min(MAX_CHUNK, slab_end - cstart);

        // Stage this chunk's labels: fully-coalesced global loads, once.
        for (int i = threadIdx.x; i < clen; i += ACC_THREADS)
            s_lab[i] = labels[cstart + i];
        __syncthreads();

        const float* fbase = feats + (size_t)cstart * DIMS + lane * 8;

        // ---- main loop: warp w owns local rows w, w+8, ...; unroll x2 ----
        int local = wid;
        for (; local + 8 < clen; local += 16) {
            float v0[8], v1[8];
            ldg256(fbase + (size_t)local * DIMS, v0);
            ldg256(fbase + (size_t)(local + 8) * DIMS, v1);
            const int l0 = s_lab[local];          // LDS broadcast, warp-uniform
            const int l1 = s_lab[local + 8];

            if (l0 == 0)      { ACC8(a0, v0); cnt0++; }
            else if (l0 == 1) { ACC8(a1, v0); cnt1++; }
            else if (l0 == 2) { ACC8(a2, v0); cnt2++; }
            else              { ACC8(a3, v0); cnt3++; }

            if (l1 == 0)      { ACC8(a0, v1); cnt0++; }
            else if (l1 == 1) { ACC8(a1, v1); cnt1++; }
            else if (l1 == 2) { ACC8(a2, v1); cnt2++; }
            else              { ACC8(a3, v1); cnt3++; }
        }
        for (; local < clen; local += 8) {
            float v[8];
            ldg256(fbase + (size_t)local * DIMS, v);
            const int lab = s_lab[local];
            if (lab == 0)      { ACC8(a0, v); cnt0++; }
            else if (lab == 1) { ACC8(a1, v); cnt1++; }
            else if (lab == 2) { ACC8(a2, v); cnt2++; }
            else               { ACC8(a3, v); cnt3++; }
        }
        __syncthreads();                  // chunk done before re-staging
    }

    // ---- block reduction across the 8 warps, per class, then atomics ----
    __shared__ float sred[8 * DIMS];     // 8 KB

    float* accs[4] = {a0, a1, a2, a3};
    #pragma unroll
    for (int k = 0; k < NUM_CLASSES; k++) {
        float* acc = accs[k];
        #pragma unroll
        for (int j = 0; j < 8; j++)
            sred[wid * DIMS + lane * 8 + j] = acc[j];
        __syncthreads();
        {
            const int col = threadIdx.x;         // 0..255
            float s = 0.f;
            #pragma unroll
            for (int w = 0; w < 8; w++)
                s += sred[w * DIMS + col];
            atomicAdd(&g_sums[k * DIMS + col], s);
        }
        __syncthreads();
    }

    // Counts: lane 0 of each warp holds them; reduce via shared.
    __shared__ int scnt[8][NUM_CLASSES];
    if (lane == 0) {
        scnt[wid][0] = cnt0; scnt[wid][1] = cnt1;
        scnt[wid][2] = cnt2; scnt[wid][3] = cnt3;
    }
    __syncthreads();
    if (threadIdx.x < NUM_CLASSES) {
        int s = 0;
        #pragma unroll
        for (int w = 0; w < 8; w++) s += scnt[w][threadIdx.x];
        atomicAdd(&g_counts[threadIdx.x], (float)s);
    }
}

// One block per class: mean, L2 norm (block reduce), normalize, write out.
// Tail: re-zero the scratch so the next graph replay sees zeroed accumulators.
__global__ __launch_bounds__(DIMS)
void finalize_kernel(float* __restrict__ out, int out_size) {
    const int k = blockIdx.x;       // class
    const int t = threadIdx.x;      // dim 0..255
    const int lane = t & 31, wid = t >> 5;

    const float cnt = g_counts[k];
    const float mean = g_sums[k * DIMS + t] / cnt;

    // Block reduction of mean*mean
    float v = mean * mean;
    #pragma unroll
    for (int off = 16; off > 0; off >>= 1)
        v += __shfl_down_sync(0xFFFFFFFFu, v, off);

    __shared__ float warpsum[8];
    if (lane == 0) warpsum[wid] = v;
    __syncthreads();
    __shared__ float s_norm;
    if (t == 0) {
        float s = 0.f;
        #pragma unroll
        for (int i = 0; i < 8; i++) s += warpsum[i];
        s_norm = fmaxf(sqrtf(s), 1e-12f);
    }
    __syncthreads();

    out[k * DIMS + t] = mean / s_norm;

    // target = arange(4); write as float values if the out buffer includes it.
    if (t == 0 && out_size >= NUM_CLASSES * DIMS + NUM_CLASSES) {
        out[NUM_CLASSES * DIMS + k] = (float)k;
    }

    // Re-zero scratch for the next replay (all reads above are done).
    g_sums[k * DIMS + t] = 0.0f;
    if (t == 0) g_counts[k] = 0.0f;
}

extern "C" void kernel_launch(void* const* d_in, const int* in_sizes, int n_in,
                              void* d_out, int out_size) {
    const float* feats = (const float*)d_in[0];
    const int* labels = (const int*)d_in[1];
    const int n_rows = in_sizes[1];          // labels element count = row count
    float* out = (float*)d_out;

    accum_kernel<<<ACC_GRID, ACC_THREADS>>>(feats, labels, n_rows);
    finalize_kernel<<<NUM_CLASSES, DIMS>>>(out, out_size);
}